// round 1
// baseline (speedup 1.0000x reference)
#include <cuda_runtime.h>
#include <cstdint>
#include <math.h>

#define N_IMG   4
#define N_ANCH  76725
#define N_CLS   80
#define PRE     512
#define BUFN    4096
#define NBIN    16384
#define MAXPC   100
#define MAXD    100

// ---------------- scratch (device globals; no runtime allocation) ----------------
__device__ float  g_scores[(size_t)N_IMG * N_CLS * N_ANCH];   // sigmoid scores [img][cls][anchor]
__device__ float4 g_boxes[(size_t)N_IMG * N_ANCH];            // decoded xywh   [img][anchor]
__device__ float  g_cls_scores[N_IMG * N_CLS * MAXPC];        // per-class NMS survivors (sorted)
__device__ float4 g_cls_boxes [N_IMG * N_CLS * MAXPC];

// ---------------- kernel 1: sigmoid-transpose + anchor decode ----------------
__global__ __launch_bounds__(256) void k_prep(const float* __restrict__ pred) {
    __shared__ float tile[32 * 85];   // 32 anchors x 84 floats, padded to 85 (bank-conflict free)
    int a0  = blockIdx.x * 32;
    int img = blockIdx.y;
    int na  = min(32, N_ANCH - a0);
    int tid = threadIdx.x;

    const float* src = pred + ((size_t)img * N_ANCH + a0) * 84;
    for (int i = tid; i < na * 84; i += 256)
        tile[(i / 84) * 85 + (i % 84)] = src[i];
    __syncthreads();

    // transposed sigmoid scores, coalesced 128B stores per class
    for (int idx = tid; idx < N_CLS * 32; idx += 256) {
        int c = idx >> 5, la = idx & 31;
        if (la < na) {
            float x = tile[la * 85 + 4 + c];
            g_scores[((size_t)(img * N_CLS + c)) * N_ANCH + a0 + la] = 1.0f / (1.0f + expf(-x));
        }
    }

    // anchor + box decode (xywh)
    if (tid < na) {
        int a = a0 + tid;
        int off, fw, stride;
        if      (a < 57600) { off = 0;     fw = 80; stride = 8;   }
        else if (a < 72000) { off = 57600; fw = 40; stride = 16;  }
        else if (a < 75600) { off = 72000; fw = 20; stride = 32;  }
        else if (a < 76500) { off = 75600; fw = 10; stride = 64;  }
        else                { off = 76500; fw = 5;  stride = 128; }
        int rem  = a - off;
        int cell = rem / 9, k = rem - cell * 9;
        int iy = cell / fw, ix = cell - iy * fw;
        float sf    = (float)stride;
        float area  = 16.0f * sf * sf;                       // (4*stride)^2
        float ratio = (k < 3) ? 0.5f : ((k < 6) ? 1.0f : 2.0f);
        int   si    = k % 3;
        float scale = (si == 0) ? 1.0f : ((si == 1) ? 1.2599210498948732f : 1.5874010519681994f);
        float hh = sqrtf(area / ratio);
        float ww = area / hh;
        float cx = (ix + 0.5f) * sf;
        float cy = (iy + 0.5f) * sf;
        float aw = scale * ww, ah = scale * hh;
        float p0 = tile[tid * 85 + 0] * 0.1f, p1 = tile[tid * 85 + 1] * 0.1f;
        float p2 = tile[tid * 85 + 2] * 0.2f, p3 = tile[tid * 85 + 3] * 0.2f;
        float4 b;
        b.x = p0 * aw + cx;
        b.y = p1 * ah + cy;
        b.z = expf(p2) * aw;
        b.w = expf(p3) * ah;
        g_boxes[(size_t)img * N_ANCH + a] = b;
    }
}

// ---------------- kernel 2: per (img,class) exact top-512 + NMS + top-100 ----------------
// dynamic smem layout (bytes):
//   [0,65536)      phase1: uint32 hist[16384]
//                  phase4+: float4 sxy[512] (8K) | float4 sxyw[512] @8192 (8K)
//                           float ssc[512] @16384 | float sar[512] @18432
//                           uint32 mask[512*16] @20480 (32K) -> ends 53248
//   [65536,98304)  u64 keys[4096]
//   [98304,100356) uint32 sufp[513]
//   [100356,100388) uint32 scal[8]
__global__ __launch_bounds__(512) void k_nms() {
    extern __shared__ char smem[];
    uint32_t* hist = (uint32_t*)smem;
    float4*   sxy  = (float4*)smem;
    float4*   sxyw = (float4*)(smem + 8192);
    float*    ssc  = (float*) (smem + 16384);
    float*    sar  = (float*) (smem + 18432);
    uint32_t* mask = (uint32_t*)(smem + 20480);
    unsigned long long* keys = (unsigned long long*)(smem + 65536);
    uint32_t* sufp = (uint32_t*)(smem + 98304);
    uint32_t* scal = (uint32_t*)(smem + 100356);

    int tid = threadIdx.x;
    size_t base = (size_t)blockIdx.x * N_ANCH;   // blockIdx.x = img*80 + cls
    int img = blockIdx.x / N_CLS;

    // ---- phase 1: 14-bit histogram of monotone float keys (all scores positive) ----
    for (int i = tid; i < NBIN; i += 512) hist[i] = 0;
    __syncthreads();
    for (int a = tid; a < N_ANCH; a += 512) {
        uint32_t m = __float_as_uint(g_scores[base + a]) | 0x80000000u;
        atomicAdd(&hist[m >> 18], 1u);
    }
    __syncthreads();

    // suffix-sum to find threshold bin of the 512th-largest
    {
        uint32_t s = 0;
        #pragma unroll
        for (int b = 0; b < 32; b++) s += hist[tid * 32 + b];
        sufp[tid] = s;
    }
    __syncthreads();
    if (tid == 0) {
        uint32_t run = 0;
        for (int t = 511; t >= 0; t--) { run += sufp[t]; uint32_t tmp = sufp[t]; sufp[t] = run; (void)tmp; }
        sufp[512] = 0;
    }
    __syncthreads();
    {
        uint32_t cur = sufp[tid], nxt = sufp[tid + 1];
        if (cur >= PRE && nxt < PRE) {
            uint32_t run = nxt;
            int T = tid * 32;
            for (int b = 31; b >= 0; b--) {
                run += hist[tid * 32 + b];
                if (run >= PRE) { T = tid * 32 + b; break; }
            }
            scal[0] = (uint32_t)T << 18;
            scal[1] = run;
        }
        if (tid == 0) scal[3] = 0;
    }
    __syncthreads();
    uint32_t thr = scal[0];

    // ---- phase 2: compaction of candidates (score-mono >= threshold) ----
    for (int a = tid; a < N_ANCH; a += 512) {
        uint32_t m = __float_as_uint(g_scores[base + a]) | 0x80000000u;
        if (m >= thr) {
            uint32_t p = atomicAdd(&scal[3], 1u);
            if (p < BUFN)
                keys[p] = ((unsigned long long)m << 32) | (uint32_t)(~(uint32_t)a);
        }
    }
    __syncthreads();
    int C = (int)min(scal[3], (uint32_t)BUFN);
    for (int i = tid; i < BUFN; i += 512) if (i >= C) keys[i] = 0ull;
    __syncthreads();

    // ---- phase 3: bitonic sort (ascending); top-512 = tail ----
    for (int k = 2; k <= BUFN; k <<= 1) {
        for (int j = k >> 1; j > 0; j >>= 1) {
            for (int i = tid; i < BUFN; i += 512) {
                int l = i ^ j;
                if (l > i) {
                    unsigned long long x = keys[i], y = keys[l];
                    bool up = ((i & k) == 0);
                    if (up ? (x > y) : (x < y)) { keys[i] = y; keys[l] = x; }
                }
            }
            __syncthreads();
        }
    }

    // ---- phase 4: gather top-512 (rank tid), stage boxes/scores in smem ----
    {
        unsigned long long key = keys[BUFN - 1 - tid];
        uint32_t a = ~((uint32_t)key);
        uint32_t m = (uint32_t)(key >> 32);
        float s = __uint_as_float(m ^ 0x80000000u);
        float4 b = g_boxes[(size_t)img * N_ANCH + a];
        float x1 = b.x - b.z * 0.5f, y1 = b.y - b.w * 0.5f;
        float x2 = b.x + b.z * 0.5f, y2 = b.y + b.w * 0.5f;
        float4 e; e.x = x1; e.y = y1; e.z = x2; e.w = y2;
        sxyw[tid] = b;
        sxy[tid]  = e;
        ssc[tid]  = s;
        sar[tid]  = (x2 - x1) * (y2 - y1);
    }
    __syncthreads();

    // ---- phase 5: upper-triangular IoU>0.5 bitmask (warp w only needs rows i<=32w+31) ----
    {
        float4 me = sxy[tid];
        float  aj = sar[tid];
        int imax = (tid | 31);            // warp-uniform
        for (int i = 0; i <= imax; i++) {
            float4 bi = sxy[i];
            float lx = fmaxf(bi.x, me.x), ly = fmaxf(bi.y, me.y);
            float rx = fminf(bi.z, me.z), ry = fminf(bi.w, me.w);
            float w = fmaxf(rx - lx, 0.0f), h = fmaxf(ry - ly, 0.0f);
            float inter = w * h;
            float un = fmaxf(sar[i] + aj - inter, 1e-8f);
            bool bit = (inter > 0.5f * un) && (tid > i);
            uint32_t bm = __ballot_sync(0xFFFFFFFFu, bit);
            if ((tid & 31) == 0) mask[i * 16 + (tid >> 5)] = bm;
        }
    }
    __syncthreads();

    // ---- phase 6: single-warp greedy bitmap NMS + per-class top-100 emit ----
    if (tid < 32) {
        int l = tid;
        uint32_t validw = 0;
        if (l < 16) {
            for (int b = 0; b < 32; b++)
                validw |= (ssc[l * 32 + b] > 0.05f) ? (1u << b) : 0u;
        }
        uint32_t keepw = 0xFFFFFFFFu;
        for (int i = 0; i < PRE; i++) {
            int wi = i >> 5;
            uint32_t kv = __shfl_sync(0xFFFFFFFFu, keepw & validw, wi);
            if ((kv >> (i & 31)) & 1u) {
                uint32_t mw = (l < 16 && l >= wi) ? mask[i * 16 + l] : 0u;
                keepw &= ~mw;
            }
        }
        keepw &= validw;
        if (l >= 16) keepw = 0;
        uint32_t pc = __popc(keepw);
        uint32_t incl = pc;
        for (int d = 1; d < 32; d <<= 1) {
            uint32_t n = __shfl_up_sync(0xFFFFFFFFu, incl, d);
            if (tid >= d) incl += n;
        }
        uint32_t offs  = incl - pc;
        uint32_t total = __shfl_sync(0xFFFFFFFFu, incl, 15);
        if (l < 16) {
            uint32_t slot = offs;
            uint32_t kw = keepw;
            while (kw) {
                int b = __ffs(kw) - 1;
                kw &= kw - 1;
                if (slot < MAXPC) {
                    int gi = blockIdx.x * MAXPC + (int)slot;
                    int r  = l * 32 + b;
                    g_cls_scores[gi] = ssc[r];
                    g_cls_boxes[gi]  = sxyw[r];
                }
                slot++;
            }
        }
        if (tid == 0) scal[4] = total;
    }
    __syncthreads();
    uint32_t total = scal[4];
    if (tid < MAXPC && (uint32_t)tid >= total) {
        int gi = blockIdx.x * MAXPC + tid;
        g_cls_scores[gi] = -1.0f;
        g_cls_boxes[gi]  = make_float4(-1.0f, -1.0f, -1.0f, -1.0f);
    }
}

// ---------------- kernel 3: per-image merge (8000 -> top-100) + output ----------------
__global__ __launch_bounds__(512) void k_merge(float* __restrict__ out) {
    extern __shared__ char smem[];
    unsigned long long* keys = (unsigned long long*)smem;   // 8192 * 8 = 65536
    uint32_t* cnt = (uint32_t*)(smem + 65536);
    int tid = threadIdx.x;
    int img = blockIdx.x;
    if (tid == 0) cnt[0] = 0;

    const int TOT = N_CLS * MAXPC;   // 8000
    for (int e = tid; e < 8192; e += 512) {
        unsigned long long key = 0ull;
        if (e < TOT) {
            uint32_t b = __float_as_uint(g_cls_scores[img * TOT + e]);
            uint32_t m = (b & 0x80000000u) ? ~b : (b | 0x80000000u);
            key = ((unsigned long long)m << 32) | (uint32_t)(~(uint32_t)e);
        }
        keys[e] = key;
    }
    __syncthreads();

    for (int k = 2; k <= 8192; k <<= 1) {
        for (int j = k >> 1; j > 0; j >>= 1) {
            for (int i = tid; i < 8192; i += 512) {
                int l = i ^ j;
                if (l > i) {
                    unsigned long long x = keys[i], y = keys[l];
                    bool up = ((i & k) == 0);
                    if (up ? (x > y) : (x < y)) { keys[i] = y; keys[l] = x; }
                }
            }
            __syncthreads();
        }
    }

    if (tid < MAXD) {
        unsigned long long key = keys[8191 - tid];
        uint32_t e = ~((uint32_t)key);
        float s  = g_cls_scores[img * TOT + e];
        float4 b = g_cls_boxes[img * TOT + e];
        bool valid = (s >= 0.05f);
        int cls = (int)(e / MAXPC);
        int o = img * MAXD + tid;
        float4 ob = valid ? b : make_float4(-1.0f, -1.0f, -1.0f, -1.0f);
        ((float4*)out)[o]  = ob;                          // fb: out[0..1600)
        out[1600 + o] = valid ? s : -1.0f;                // fs
        out[2000 + o] = valid ? (float)cls : -1.0f;       // fc
        if (valid) atomicAdd(cnt, 1u);
    }
    __syncthreads();
    if (tid == 0) out[2400 + img] = (float)cnt[0];        // count
}

// ---------------- launcher ----------------
extern "C" void kernel_launch(void* const* d_in, const int* in_sizes, int n_in,
                              void* d_out, int out_size) {
    // inputs: images (4,640,640,3) [unused beyond shape], predictions (4,76725,84)
    const float* pred = (const float*)d_in[1];
    if (n_in >= 1 && in_sizes[0] == N_IMG * N_ANCH * 84)
        pred = (const float*)d_in[0];

    static const int NMS_SMEM   = 100416;
    static const int MERGE_SMEM = 65536 + 16;
    cudaFuncSetAttribute(k_nms,   cudaFuncAttributeMaxDynamicSharedMemorySize, NMS_SMEM);
    cudaFuncSetAttribute(k_merge, cudaFuncAttributeMaxDynamicSharedMemorySize, MERGE_SMEM);

    dim3 g1((N_ANCH + 31) / 32, N_IMG);
    k_prep<<<g1, 256>>>(pred);
    k_nms<<<N_IMG * N_CLS, 512, NMS_SMEM>>>();
    k_merge<<<N_IMG, 512, MERGE_SMEM>>>((float*)d_out);
}

// round 3
// speedup vs baseline: 1.8629x; 1.8629x over previous
#include <cuda_runtime.h>
#include <cstdint>
#include <math.h>

#define N_IMG   4
#define N_ANCH  76725
#define N_CLS   80
#define PRE     512
#define BUF_NMS 2048
#define BUF_MRG 1024
#define NBIN    16384
#define MAXPC   100
#define MAXD    100

// k_nms smem layout (bytes):
//  hist [0,65536)  (phases 1-2) ; overlaid later by:
//    keys@0 (2048*8=16384), sxy@16384 (8K), sxyw@24576 (8K),
//    ssc@32768 (2K), sar@34816 (2K), mask@36864 (32K) -> 69632
//  sufp@69632 (2052), wsum@71684 (64), wsuf@71748 (64), scal@71812 (32)
#define NMS_SMEM 71872
// k_merge smem: hist[0,65536) / keys@0 (1024*8), sufp@65536, wsum@67588, wsuf@67652, scal@67716
#define MRG_SMEM 67760

// ---------------- scratch (device globals) ----------------
__device__ float  g_scores[(size_t)N_IMG * N_CLS * N_ANCH];
__device__ float4 g_boxes[(size_t)N_IMG * N_ANCH];
__device__ float  g_cls_scores[N_IMG * N_CLS * MAXPC];
__device__ float4 g_cls_boxes [N_IMG * N_CLS * MAXPC];

// ---------------- kernel 1: sigmoid-transpose + anchor decode ----------------
__global__ __launch_bounds__(256) void k_prep(const float* __restrict__ pred) {
    __shared__ float tile[32 * 85];
    int a0  = blockIdx.x * 32;
    int img = blockIdx.y;
    int na  = min(32, N_ANCH - a0);
    int tid = threadIdx.x;

    const float4* src = (const float4*)(pred + ((size_t)img * N_ANCH + a0) * 84);
    int nv = na * 21;
    for (int i = tid; i < nv; i += 256) {
        float4 v = src[i];
        int row = i / 21, c4 = (i - row * 21) * 4;
        float* t = &tile[row * 85 + c4];
        t[0] = v.x; t[1] = v.y; t[2] = v.z; t[3] = v.w;
    }
    __syncthreads();

    for (int idx = tid; idx < N_CLS * 32; idx += 256) {
        int c = idx >> 5, la = idx & 31;
        if (la < na) {
            float x = tile[la * 85 + 4 + c];
            g_scores[((size_t)(img * N_CLS + c)) * N_ANCH + a0 + la] =
                __fdividef(1.0f, 1.0f + __expf(-x));
        }
    }

    if (tid < na) {
        int a = a0 + tid;
        int off, fw, stride;
        if      (a < 57600) { off = 0;     fw = 80; stride = 8;   }
        else if (a < 72000) { off = 57600; fw = 40; stride = 16;  }
        else if (a < 75600) { off = 72000; fw = 20; stride = 32;  }
        else if (a < 76500) { off = 75600; fw = 10; stride = 64;  }
        else                { off = 76500; fw = 5;  stride = 128; }
        int rem  = a - off;
        int cell = rem / 9, k = rem - cell * 9;
        int iy = cell / fw, ix = cell - iy * fw;
        float sf    = (float)stride;
        float area  = 16.0f * sf * sf;
        float ratio = (k < 3) ? 0.5f : ((k < 6) ? 1.0f : 2.0f);
        int   si    = k % 3;
        float scale = (si == 0) ? 1.0f : ((si == 1) ? 1.2599210498948732f : 1.5874010519681994f);
        float hh = sqrtf(area / ratio);
        float ww = area / hh;
        float cx = (ix + 0.5f) * sf;
        float cy = (iy + 0.5f) * sf;
        float aw = scale * ww, ah = scale * hh;
        float p0 = tile[tid * 85 + 0] * 0.1f, p1 = tile[tid * 85 + 1] * 0.1f;
        float p2 = tile[tid * 85 + 2] * 0.2f, p3 = tile[tid * 85 + 3] * 0.2f;
        float4 b;
        b.x = p0 * aw + cx;
        b.y = p1 * ah + cy;
        b.z = __expf(p2) * aw;
        b.w = __expf(p3) * ah;
        g_boxes[(size_t)img * N_ANCH + a] = b;
    }
}

// parallel inclusive SUFFIX scan of 512 per-thread values -> sufp[tid]; sufp[512]=0
__device__ __forceinline__ void suffix_scan_512(uint32_t v, uint32_t* sufp,
                                                uint32_t* wsum, uint32_t* wsuf, int tid) {
    int lane = tid & 31, wid = tid >> 5;
    uint32_t incl = v;
    #pragma unroll
    for (int d = 1; d < 32; d <<= 1) {
        uint32_t n = __shfl_down_sync(0xFFFFFFFFu, incl, d);
        if (lane + d < 32) incl += n;
    }
    if (lane == 0) wsum[wid] = incl;
    __syncthreads();
    if (tid < 16) {
        uint32_t x = wsum[tid];
        #pragma unroll
        for (int d = 1; d < 16; d <<= 1) {
            uint32_t n = __shfl_down_sync(0x0000FFFFu, x, d);
            if (tid + d < 16) x += n;
        }
        wsuf[tid] = x;
    }
    __syncthreads();
    uint32_t below = (wid < 15) ? wsuf[wid + 1] : 0u;
    sufp[tid] = incl + below;
    if (tid == 0) sufp[512] = 0;
    __syncthreads();
}

// ---------------- kernel 2: per (img,class) exact top-512 + NMS + top-100 ----------------
__global__ __launch_bounds__(512, 3) void k_nms() {
    extern __shared__ char smem[];
    uint32_t* hist = (uint32_t*)smem;
    unsigned long long* keys = (unsigned long long*)smem;   // 2048 keys, overlays hist
    float4*   sxy  = (float4*)(smem + 16384);
    float4*   sxyw = (float4*)(smem + 24576);
    float*    ssc  = (float*) (smem + 32768);
    float*    sar  = (float*) (smem + 34816);
    uint32_t* mask = (uint32_t*)(smem + 36864);
    uint32_t* sufp = (uint32_t*)(smem + 69632);
    uint32_t* wsum = (uint32_t*)(smem + 71684);
    uint32_t* wsuf = (uint32_t*)(smem + 71748);
    uint32_t* scal = (uint32_t*)(smem + 71812);

    int tid = threadIdx.x;
    size_t base = (size_t)blockIdx.x * N_ANCH;   // blockIdx.x = img*80 + cls
    int img = blockIdx.x / N_CLS;

    // ---- phase 1: 14-bit histogram of monotone float keys ----
    {
        uint4 z = make_uint4(0, 0, 0, 0);
        uint4* h4 = (uint4*)hist;
        for (int i = tid; i < NBIN / 4; i += 512) h4[i] = z;
    }
    __syncthreads();
    for (int a = tid; a < N_ANCH; a += 512) {
        uint32_t m = __float_as_uint(g_scores[base + a]) | 0x80000000u;
        atomicAdd(&hist[m >> 18], 1u);
    }
    __syncthreads();

    uint32_t v = 0;
    #pragma unroll
    for (int b = 0; b < 32; b++) v += hist[tid * 32 + ((b + tid) & 31)];
    suffix_scan_512(v, sufp, wsum, wsuf, tid);

    {
        uint32_t cur = sufp[tid], nxt = sufp[tid + 1];
        if (cur >= PRE && nxt < PRE) {
            uint32_t run = nxt;
            int T = tid * 32;
            for (int b = 31; b >= 0; b--) {
                run += hist[tid * 32 + b];
                if (run >= PRE) { T = tid * 32 + b; break; }
            }
            scal[0] = (uint32_t)T << 18;
        }
        if (tid == 0) scal[3] = 0;
    }
    __syncthreads();
    uint32_t thr = scal[0];

    // ---- phase 2: compaction ----
    for (int a = tid; a < N_ANCH; a += 512) {
        uint32_t m = __float_as_uint(g_scores[base + a]) | 0x80000000u;
        if (m >= thr) {
            uint32_t p = atomicAdd(&scal[3], 1u);
            if (p < BUF_NMS)
                keys[p] = ((unsigned long long)m << 32) | (uint32_t)(~(uint32_t)a);
        }
    }
    __syncthreads();
    int C = (int)min(scal[3], (uint32_t)BUF_NMS);
    for (int i = tid; i < BUF_NMS; i += 512) if (i >= C) keys[i] = 0ull;
    __syncthreads();

    // ---- phase 3: bitonic sort 2048 (ascending); top-512 = tail ----
    for (int k = 2; k <= BUF_NMS; k <<= 1) {
        for (int j = k >> 1; j > 0; j >>= 1) {
            for (int i = tid; i < BUF_NMS; i += 512) {
                int l = i ^ j;
                if (l > i) {
                    unsigned long long x = keys[i], y = keys[l];
                    bool up = ((i & k) == 0);
                    if (up ? (x > y) : (x < y)) { keys[i] = y; keys[l] = x; }
                }
            }
            __syncthreads();
        }
    }

    // ---- phase 4: gather top-512 (rank tid) ----
    {
        unsigned long long key = keys[BUF_NMS - 1 - tid];
        uint32_t a = ~((uint32_t)key);
        uint32_t m = (uint32_t)(key >> 32);
        float s = __uint_as_float(m ^ 0x80000000u);
        float4 b = g_boxes[(size_t)img * N_ANCH + a];
        float x1 = b.x - b.z * 0.5f, y1 = b.y - b.w * 0.5f;
        float x2 = b.x + b.z * 0.5f, y2 = b.y + b.w * 0.5f;
        float4 e; e.x = x1; e.y = y1; e.z = x2; e.w = y2;
        sxyw[tid] = b;
        sxy[tid]  = e;
        ssc[tid]  = s;
        sar[tid]  = (x2 - x1) * (y2 - y1);
    }
    __syncthreads();

    // ---- phase 5: upper-triangular IoU>0.5 bitmask ----
    {
        float4 me = sxy[tid];
        float  aj = sar[tid];
        int imax = (tid | 31);
        for (int i = 0; i <= imax; i++) {
            float4 bi = sxy[i];
            float lx = fmaxf(bi.x, me.x), ly = fmaxf(bi.y, me.y);
            float rx = fminf(bi.z, me.z), ry = fminf(bi.w, me.w);
            float w = fmaxf(rx - lx, 0.0f), h = fmaxf(ry - ly, 0.0f);
            float inter = w * h;
            float un = fmaxf(sar[i] + aj - inter, 1e-8f);
            bool bit = (inter > 0.5f * un) && (tid > i);
            uint32_t bm = __ballot_sync(0xFFFFFFFFu, bit);
            if ((tid & 31) == 0) mask[i * 16 + (tid >> 5)] = bm;
        }
    }
    __syncthreads();

    // ---- phase 6: chunked single-warp greedy NMS ----
    if (tid < 32) {
        const uint32_t F = 0xFFFFFFFFu;
        int l = tid;
        uint32_t validw = 0;
        if (l < 16) {
            #pragma unroll
            for (int b = 0; b < 32; b++)
                validw |= (ssc[l * 32 + b] > 0.05f) ? (1u << b) : 0u;
        }
        uint32_t keepw = 0xFFFFFFFFu;
        #pragma unroll 1
        for (int g = 0; g < 16; g++) {
            uint32_t vwg  = __shfl_sync(F, validw, g);
            uint32_t kloc = __shfl_sync(F, keepw, g);
            if (l == g) {
                #pragma unroll
                for (int B = 0; B < 4; B++) {
                    uint32_t mm[8];
                    #pragma unroll
                    for (int j = 0; j < 8; j++) mm[j] = mask[(32 * g + 8 * B + j) * 16 + g];
                    #pragma unroll
                    for (int j = 0; j < 8; j++) {
                        int b = 8 * B + j;
                        if (((kloc >> b) & 1u) && ((vwg >> b) & 1u)) kloc &= ~mm[j];
                    }
                }
            }
            uint32_t alive = __shfl_sync(F, kloc & vwg, g);
            if (l == g) keepw = kloc;
            if (l > g && l < 16) {
                uint32_t sup = 0;
                #pragma unroll
                for (int B = 0; B < 4; B++) {
                    uint32_t mm[8];
                    #pragma unroll
                    for (int j = 0; j < 8; j++) mm[j] = mask[(32 * g + 8 * B + j) * 16 + l];
                    #pragma unroll
                    for (int j = 0; j < 8; j++) if ((alive >> (8 * B + j)) & 1u) sup |= mm[j];
                }
                keepw &= ~sup;
            }
        }
        keepw &= validw;
        if (l >= 16) keepw = 0;

        uint32_t pc = __popc(keepw);
        uint32_t incl = pc;
        #pragma unroll
        for (int d = 1; d < 32; d <<= 1) {
            uint32_t n = __shfl_up_sync(F, incl, d);
            if (tid >= d) incl += n;
        }
        uint32_t offs  = incl - pc;
        uint32_t total = __shfl_sync(F, incl, 15);
        if (l < 16) {
            uint32_t slot = offs;
            uint32_t kw = keepw;
            while (kw) {
                int b = __ffs(kw) - 1;
                kw &= kw - 1;
                if (slot < MAXPC) {
                    int gi = blockIdx.x * MAXPC + (int)slot;
                    int r  = l * 32 + b;
                    g_cls_scores[gi] = ssc[r];
                    g_cls_boxes[gi]  = sxyw[r];
                }
                slot++;
            }
        }
        if (tid == 0) scal[4] = total;
    }
    __syncthreads();
    uint32_t total = scal[4];
    if (tid < MAXPC && (uint32_t)tid >= total) {
        int gi = blockIdx.x * MAXPC + tid;
        g_cls_scores[gi] = -1.0f;
        g_cls_boxes[gi]  = make_float4(-1.0f, -1.0f, -1.0f, -1.0f);
    }
}

// ---------------- kernel 3: per-image merge, two-level radix select ----------------
__global__ __launch_bounds__(512) void k_merge(float* __restrict__ out) {
    extern __shared__ char smem[];
    uint32_t* hist = (uint32_t*)smem;
    unsigned long long* keys = (unsigned long long*)smem;   // overlays hist after selection
    uint32_t* sufp = (uint32_t*)(smem + 65536);
    uint32_t* wsum = (uint32_t*)(smem + 67588);
    uint32_t* wsuf = (uint32_t*)(smem + 67652);
    uint32_t* scal = (uint32_t*)(smem + 67716);

    int tid = threadIdx.x;
    int img = blockIdx.x;
    const int TOT = N_CLS * MAXPC;   // 8000

    // ---- pass 1: coarse histogram on key bits [31:18] ----
    {
        uint4 z = make_uint4(0, 0, 0, 0);
        uint4* h4 = (uint4*)hist;
        for (int i = tid; i < NBIN / 4; i += 512) h4[i] = z;
    }
    __syncthreads();
    for (int e = tid; e < TOT; e += 512) {
        uint32_t b = __float_as_uint(g_cls_scores[img * TOT + e]);
        uint32_t m = (b & 0x80000000u) ? ~b : (b | 0x80000000u);
        atomicAdd(&hist[m >> 18], 1u);
    }
    __syncthreads();

    uint32_t v = 0;
    #pragma unroll
    for (int b = 0; b < 32; b++) v += hist[tid * 32 + ((b + tid) & 31)];
    suffix_scan_512(v, sufp, wsum, wsuf, tid);

    {
        uint32_t cur = sufp[tid], nxt = sufp[tid + 1];
        if (cur >= MAXD && nxt < MAXD) {
            uint32_t run = nxt;
            int T = tid * 32;
            uint32_t above = nxt;
            for (int b = 31; b >= 0; b--) {
                uint32_t h = hist[tid * 32 + b];
                run += h;
                if (run >= MAXD) { T = tid * 32 + b; above = run - h; break; }
            }
            scal[5] = (uint32_t)T;     // coarse threshold bin
            scal[1] = above;           // count strictly above bin T
        }
        if (tid == 0) { scal[3] = 0; scal[4] = 0; }
    }
    __syncthreads();
    uint32_t T1    = scal[5];
    uint32_t above = scal[1];
    uint32_t need  = MAXD - above;     // how many to take from bin T1 (>=1)

    // ---- pass 2: refine within bin T1 on key bits [17:4] ----
    {
        uint4 z = make_uint4(0, 0, 0, 0);
        uint4* h4 = (uint4*)hist;
        for (int i = tid; i < NBIN / 4; i += 512) h4[i] = z;
    }
    __syncthreads();
    for (int e = tid; e < TOT; e += 512) {
        uint32_t b = __float_as_uint(g_cls_scores[img * TOT + e]);
        uint32_t m = (b & 0x80000000u) ? ~b : (b | 0x80000000u);
        if ((m >> 18) == T1) atomicAdd(&hist[(m >> 4) & 0x3FFFu], 1u);
    }
    __syncthreads();

    v = 0;
    #pragma unroll
    for (int b = 0; b < 32; b++) v += hist[tid * 32 + ((b + tid) & 31)];
    suffix_scan_512(v, sufp, wsum, wsuf, tid);

    {
        uint32_t cur = sufp[tid], nxt = sufp[tid + 1];
        if (cur >= need && nxt < need) {
            uint32_t run = nxt;
            int T = tid * 32;
            for (int b = 31; b >= 0; b--) {
                run += hist[tid * 32 + b];
                if (run >= need) { T = tid * 32 + b; break; }
            }
            scal[2] = (uint32_t)T;
        }
    }
    __syncthreads();
    uint32_t T2 = scal[2];

    // ---- compaction: exact candidate set (~<=110 entries) ----
    for (int e = tid; e < TOT; e += 512) {
        uint32_t b = __float_as_uint(g_cls_scores[img * TOT + e]);
        uint32_t m = (b & 0x80000000u) ? ~b : (b | 0x80000000u);
        uint32_t b1 = m >> 18;
        bool cand = (b1 > T1) || (b1 == T1 && ((m >> 4) & 0x3FFFu) >= T2);
        if (cand) {
            uint32_t p = atomicAdd(&scal[3], 1u);
            if (p < BUF_MRG)
                keys[p] = ((unsigned long long)m << 32) | (uint32_t)(~(uint32_t)e);
        }
    }
    __syncthreads();
    int C = (int)min(scal[3], (uint32_t)BUF_MRG);
    for (int i = tid; i < BUF_MRG; i += 512) if (i >= C) keys[i] = 0ull;
    __syncthreads();

    // ---- bitonic sort 1024 ----
    for (int k = 2; k <= BUF_MRG; k <<= 1) {
        for (int j = k >> 1; j > 0; j >>= 1) {
            for (int i = tid; i < BUF_MRG; i += 512) {
                int l = i ^ j;
                if (l > i) {
                    unsigned long long x = keys[i], y = keys[l];
                    bool up = ((i & k) == 0);
                    if (up ? (x > y) : (x < y)) { keys[i] = y; keys[l] = x; }
                }
            }
            __syncthreads();
        }
    }

    if (tid < MAXD) {
        unsigned long long key = keys[BUF_MRG - 1 - tid];
        uint32_t e = ~((uint32_t)key);
        float s  = g_cls_scores[img * TOT + e];
        float4 b = g_cls_boxes[img * TOT + e];
        bool valid = (s >= 0.05f);
        int cls = (int)(e / MAXPC);
        int o = img * MAXD + tid;
        float4 ob = valid ? b : make_float4(-1.0f, -1.0f, -1.0f, -1.0f);
        ((float4*)out)[o]  = ob;                          // fb
        out[1600 + o] = valid ? s : -1.0f;                // fs
        out[2000 + o] = valid ? (float)cls : -1.0f;       // fc
        if (valid) atomicAdd(&scal[4], 1u);
    }
    __syncthreads();
    if (tid == 0) out[2400 + img] = (float)scal[4];       // count
}

// ---------------- launcher ----------------
extern "C" void kernel_launch(void* const* d_in, const int* in_sizes, int n_in,
                              void* d_out, int out_size) {
    const float* pred = (const float*)d_in[1];
    if (n_in >= 1 && in_sizes[0] == N_IMG * N_ANCH * 84)
        pred = (const float*)d_in[0];

    cudaFuncSetAttribute(k_nms,   cudaFuncAttributeMaxDynamicSharedMemorySize, NMS_SMEM);
    cudaFuncSetAttribute(k_merge, cudaFuncAttributeMaxDynamicSharedMemorySize, MRG_SMEM);

    dim3 g1((N_ANCH + 31) / 32, N_IMG);
    k_prep<<<g1, 256>>>(pred);
    k_nms<<<N_IMG * N_CLS, 512, NMS_SMEM>>>();
    k_merge<<<N_IMG, 512, MRG_SMEM>>>((float*)d_out);
}

// round 4
// speedup vs baseline: 2.0686x; 1.1104x over previous
#include <cuda_runtime.h>
#include <cstdint>
#include <math.h>

#define N_IMG   4
#define N_ANCH  76725
#define N_CLS   80
#define PRE     512
#define CAND_MAX 2048
#define BUF_MRG 1024
#define NBIN    16384
#define MAXPC   100
#define MAXD    100

// logit(0.91): scores s > 0.91  <=>  x > 2.3136168
#define XTHR 2.3136168f

// k_nms smem (bytes):
//  hist [0,65536) fallback only; overlaid by:
//    keys@0 (2048*8=16384), sxy@16384 (8K), sxyw@24576 (8K),
//    ssc@32768 (2K), sar@34816 (2K), mask@36864 (32K) -> 69632
//  sufp@69632 (2052), wsum@71684, wsuf@71748, scal@71812
#define NMS_SMEM 71872
#define MRG_SMEM 67760

// ---------------- scratch (device globals) ----------------
__device__ float4 g_boxes[(size_t)N_IMG * N_ANCH];
__device__ unsigned long long g_cand[(size_t)N_IMG * N_CLS * CAND_MAX];
__device__ uint32_t g_cnt[N_IMG * N_CLS];
__device__ float  g_cls_scores[N_IMG * N_CLS * MAXPC];
__device__ float4 g_cls_boxes [N_IMG * N_CLS * MAXPC];

// ---------------- kernel 0: zero candidate counters ----------------
__global__ void k_zero() {
    int i = blockIdx.x * blockDim.x + threadIdx.x;
    if (i < N_IMG * N_CLS) g_cnt[i] = 0;
}

// ---------------- kernel 1: streaming candidate select + box decode ----------------
// one thread per float4 of pred (84 floats/anchor = 21 float4, fully coalesced)
__global__ __launch_bounds__(256) void k_prep(const float* __restrict__ pred) {
    const int TOTV = N_IMG * N_ANCH * 21;
    int g = blockIdx.x * 256 + threadIdx.x;
    if (g >= TOTV) return;
    float4 v = ((const float4*)pred)[g];

    int img = g / (N_ANCH * 21);
    int rem = g - img * (N_ANCH * 21);
    int a   = rem / 21;
    int q   = rem - a * 21;

    if (q == 0) {
        // cols 0-3: box regression -> decode
        int off, fw, stride;
        if      (a < 57600) { off = 0;     fw = 80; stride = 8;   }
        else if (a < 72000) { off = 57600; fw = 40; stride = 16;  }
        else if (a < 75600) { off = 72000; fw = 20; stride = 32;  }
        else if (a < 76500) { off = 75600; fw = 10; stride = 64;  }
        else                { off = 76500; fw = 5;  stride = 128; }
        int rem2 = a - off;
        int cell = rem2 / 9, k = rem2 - cell * 9;
        int iy = cell / fw, ix = cell - iy * fw;
        float sf    = (float)stride;
        float area  = 16.0f * sf * sf;
        float ratio = (k < 3) ? 0.5f : ((k < 6) ? 1.0f : 2.0f);
        int   si    = k % 3;
        float scale = (si == 0) ? 1.0f : ((si == 1) ? 1.2599210498948732f : 1.5874010519681994f);
        float hh = sqrtf(area / ratio);
        float ww = area / hh;
        float cx = (ix + 0.5f) * sf;
        float cy = (iy + 0.5f) * sf;
        float aw = scale * ww, ah = scale * hh;
        float4 b;
        b.x = v.x * 0.1f * aw + cx;
        b.y = v.y * 0.1f * ah + cy;
        b.z = __expf(v.z * 0.2f) * aw;
        b.w = __expf(v.w * 0.2f) * ah;
        g_boxes[(size_t)img * N_ANCH + a] = b;
    } else {
        // cols 4q..4q+3: class logits for classes 4q-4..4q-1
        float xs[4] = {v.x, v.y, v.z, v.w};
        #pragma unroll
        for (int j = 0; j < 4; j++) {
            float x = xs[j];
            if (x > XTHR) {
                int cls = 4 * q + j - 4;
                float s = __fdividef(1.0f, 1.0f + __expf(-x));
                uint32_t mono = __float_as_uint(s) | 0x80000000u;
                int list = img * N_CLS + cls;
                uint32_t idx = atomicAdd(&g_cnt[list], 1u);
                if (idx < CAND_MAX)
                    g_cand[(size_t)list * CAND_MAX + idx] =
                        ((unsigned long long)mono << 32) | (uint32_t)(~(uint32_t)a);
            }
        }
    }
}

// parallel inclusive SUFFIX scan of 512 per-thread values -> sufp[tid]; sufp[512]=0
__device__ __forceinline__ void suffix_scan_512(uint32_t v, uint32_t* sufp,
                                                uint32_t* wsum, uint32_t* wsuf, int tid) {
    int lane = tid & 31, wid = tid >> 5;
    uint32_t incl = v;
    #pragma unroll
    for (int d = 1; d < 32; d <<= 1) {
        uint32_t n = __shfl_down_sync(0xFFFFFFFFu, incl, d);
        if (lane + d < 32) incl += n;
    }
    if (lane == 0) wsum[wid] = incl;
    __syncthreads();
    if (tid < 16) {
        uint32_t x = wsum[tid];
        #pragma unroll
        for (int d = 1; d < 16; d <<= 1) {
            uint32_t n = __shfl_down_sync(0x0000FFFFu, x, d);
            if (tid + d < 16) x += n;
        }
        wsuf[tid] = x;
    }
    __syncthreads();
    uint32_t below = (wid < 15) ? wsuf[wid + 1] : 0u;
    sufp[tid] = incl + below;
    if (tid == 0) sufp[512] = 0;
    __syncthreads();
}

// ---------------- kernel 2: per (img,class) top-512 + NMS + top-100 ----------------
__global__ __launch_bounds__(512, 3) void k_nms(const float* __restrict__ pred) {
    extern __shared__ char smem[];
    uint32_t* hist = (uint32_t*)smem;                        // fallback only
    unsigned long long* keys = (unsigned long long*)smem;    // 2048 keys
    float4*   sxy  = (float4*)(smem + 16384);
    float4*   sxyw = (float4*)(smem + 24576);
    float*    ssc  = (float*) (smem + 32768);
    float*    sar  = (float*) (smem + 34816);
    uint32_t* mask = (uint32_t*)(smem + 36864);
    uint32_t* sufp = (uint32_t*)(smem + 69632);
    uint32_t* wsum = (uint32_t*)(smem + 71684);
    uint32_t* wsuf = (uint32_t*)(smem + 71748);
    uint32_t* scal = (uint32_t*)(smem + 71812);

    int tid = threadIdx.x;
    int bid = blockIdx.x;                 // img*80 + cls
    int img = bid / N_CLS;
    int cls = bid - img * N_CLS;

    uint32_t cnt = g_cnt[bid];
    int SORTN;

    if (cnt >= PRE && cnt <= CAND_MAX) {
        // ---- fast path: load precompacted candidate list ----
        SORTN = (cnt <= 1024) ? 1024 : CAND_MAX;
        const unsigned long long* src = &g_cand[(size_t)bid * CAND_MAX];
        for (int i = tid; i < SORTN; i += 512)
            keys[i] = (i < (int)cnt) ? src[i] : 0ull;
        __syncthreads();
    } else {
        // ---- exact fallback: full histogram select from pred column ----
        SORTN = CAND_MAX;
        {
            uint4 z = make_uint4(0, 0, 0, 0);
            uint4* h4 = (uint4*)hist;
            for (int i = tid; i < NBIN / 4; i += 512) h4[i] = z;
        }
        __syncthreads();
        for (int a = tid; a < N_ANCH; a += 512) {
            float x = pred[((size_t)img * N_ANCH + a) * 84 + 4 + cls];
            float s = __fdividef(1.0f, 1.0f + __expf(-x));
            uint32_t m = __float_as_uint(s) | 0x80000000u;
            atomicAdd(&hist[m >> 18], 1u);
        }
        __syncthreads();
        uint32_t v = 0;
        #pragma unroll
        for (int b = 0; b < 32; b++) v += hist[tid * 32 + ((b + tid) & 31)];
        suffix_scan_512(v, sufp, wsum, wsuf, tid);
        {
            uint32_t cur = sufp[tid], nxt = sufp[tid + 1];
            if (cur >= PRE && nxt < PRE) {
                uint32_t run = nxt;
                int T = tid * 32;
                for (int b = 31; b >= 0; b--) {
                    run += hist[tid * 32 + b];
                    if (run >= PRE) { T = tid * 32 + b; break; }
                }
                scal[0] = (uint32_t)T << 18;
            }
            if (tid == 0) scal[3] = 0;
        }
        __syncthreads();
        uint32_t thr = scal[0];
        for (int a = tid; a < N_ANCH; a += 512) {
            float x = pred[((size_t)img * N_ANCH + a) * 84 + 4 + cls];
            float s = __fdividef(1.0f, 1.0f + __expf(-x));
            uint32_t m = __float_as_uint(s) | 0x80000000u;
            if (m >= thr) {
                uint32_t p = atomicAdd(&scal[3], 1u);
                if (p < CAND_MAX)
                    keys[p] = ((unsigned long long)m << 32) | (uint32_t)(~(uint32_t)a);
            }
        }
        __syncthreads();
        int C = (int)min(scal[3], (uint32_t)CAND_MAX);
        for (int i = tid; i < CAND_MAX; i += 512) if (i >= C) keys[i] = 0ull;
        __syncthreads();
    }

    // ---- bitonic sort SORTN (ascending); top-512 = tail ----
    for (int k = 2; k <= SORTN; k <<= 1) {
        for (int j = k >> 1; j > 0; j >>= 1) {
            for (int i = tid; i < SORTN; i += 512) {
                int l = i ^ j;
                if (l > i) {
                    unsigned long long x = keys[i], y = keys[l];
                    bool up = ((i & k) == 0);
                    if (up ? (x > y) : (x < y)) { keys[i] = y; keys[l] = x; }
                }
            }
            __syncthreads();
        }
    }

    // ---- gather top-512 (rank tid) ----
    {
        unsigned long long key = keys[SORTN - 1 - tid];
        uint32_t a = ~((uint32_t)key);
        uint32_t m = (uint32_t)(key >> 32);
        float s = __uint_as_float(m ^ 0x80000000u);
        float4 b = g_boxes[(size_t)img * N_ANCH + a];
        float x1 = b.x - b.z * 0.5f, y1 = b.y - b.w * 0.5f;
        float x2 = b.x + b.z * 0.5f, y2 = b.y + b.w * 0.5f;
        float4 e; e.x = x1; e.y = y1; e.z = x2; e.w = y2;
        sxyw[tid] = b;
        sxy[tid]  = e;
        ssc[tid]  = s;
        sar[tid]  = (x2 - x1) * (y2 - y1);
    }
    __syncthreads();

    // ---- upper-triangular IoU>0.5 bitmask ----
    {
        float4 me = sxy[tid];
        float  aj = sar[tid];
        int imax = (tid | 31);
        for (int i = 0; i <= imax; i++) {
            float4 bi = sxy[i];
            float lx = fmaxf(bi.x, me.x), ly = fmaxf(bi.y, me.y);
            float rx = fminf(bi.z, me.z), ry = fminf(bi.w, me.w);
            float w = fmaxf(rx - lx, 0.0f), h = fmaxf(ry - ly, 0.0f);
            float inter = w * h;
            float un = fmaxf(sar[i] + aj - inter, 1e-8f);
            bool bit = (inter > 0.5f * un) && (tid > i);
            uint32_t bm = __ballot_sync(0xFFFFFFFFu, bit);
            if ((tid & 31) == 0) mask[i * 16 + (tid >> 5)] = bm;
        }
    }
    __syncthreads();

    // ---- chunked single-warp greedy NMS ----
    if (tid < 32) {
        const uint32_t F = 0xFFFFFFFFu;
        int l = tid;
        uint32_t validw = 0;
        if (l < 16) {
            #pragma unroll
            for (int b = 0; b < 32; b++)
                validw |= (ssc[l * 32 + b] > 0.05f) ? (1u << b) : 0u;
        }
        uint32_t keepw = 0xFFFFFFFFu;
        #pragma unroll 1
        for (int g = 0; g < 16; g++) {
            uint32_t vwg  = __shfl_sync(F, validw, g);
            uint32_t kloc = __shfl_sync(F, keepw, g);
            if (l == g) {
                #pragma unroll
                for (int B = 0; B < 4; B++) {
                    uint32_t mm[8];
                    #pragma unroll
                    for (int j = 0; j < 8; j++) mm[j] = mask[(32 * g + 8 * B + j) * 16 + g];
                    #pragma unroll
                    for (int j = 0; j < 8; j++) {
                        int b = 8 * B + j;
                        if (((kloc >> b) & 1u) && ((vwg >> b) & 1u)) kloc &= ~mm[j];
                    }
                }
            }
            uint32_t alive = __shfl_sync(F, kloc & vwg, g);
            if (l == g) keepw = kloc;
            if (l > g && l < 16) {
                uint32_t sup = 0;
                #pragma unroll
                for (int B = 0; B < 4; B++) {
                    uint32_t mm[8];
                    #pragma unroll
                    for (int j = 0; j < 8; j++) mm[j] = mask[(32 * g + 8 * B + j) * 16 + l];
                    #pragma unroll
                    for (int j = 0; j < 8; j++) if ((alive >> (8 * B + j)) & 1u) sup |= mm[j];
                }
                keepw &= ~sup;
            }
        }
        keepw &= validw;
        if (l >= 16) keepw = 0;

        uint32_t pc = __popc(keepw);
        uint32_t incl = pc;
        #pragma unroll
        for (int d = 1; d < 32; d <<= 1) {
            uint32_t n = __shfl_up_sync(F, incl, d);
            if (tid >= d) incl += n;
        }
        uint32_t offs  = incl - pc;
        uint32_t total = __shfl_sync(F, incl, 15);
        if (l < 16) {
            uint32_t slot = offs;
            uint32_t kw = keepw;
            while (kw) {
                int b = __ffs(kw) - 1;
                kw &= kw - 1;
                if (slot < MAXPC) {
                    int gi = bid * MAXPC + (int)slot;
                    int r  = l * 32 + b;
                    g_cls_scores[gi] = ssc[r];
                    g_cls_boxes[gi]  = sxyw[r];
                }
                slot++;
            }
        }
        if (tid == 0) scal[4] = total;
    }
    __syncthreads();
    uint32_t total = scal[4];
    if (tid < MAXPC && (uint32_t)tid >= total) {
        int gi = bid * MAXPC + tid;
        g_cls_scores[gi] = -1.0f;
        g_cls_boxes[gi]  = make_float4(-1.0f, -1.0f, -1.0f, -1.0f);
    }
}

// ---------------- kernel 3: per-image merge, two-level radix select ----------------
__global__ __launch_bounds__(512) void k_merge(float* __restrict__ out) {
    extern __shared__ char smem[];
    uint32_t* hist = (uint32_t*)smem;
    unsigned long long* keys = (unsigned long long*)smem;
    uint32_t* sufp = (uint32_t*)(smem + 65536);
    uint32_t* wsum = (uint32_t*)(smem + 67588);
    uint32_t* wsuf = (uint32_t*)(smem + 67652);
    uint32_t* scal = (uint32_t*)(smem + 67716);

    int tid = threadIdx.x;
    int img = blockIdx.x;
    const int TOT = N_CLS * MAXPC;

    {
        uint4 z = make_uint4(0, 0, 0, 0);
        uint4* h4 = (uint4*)hist;
        for (int i = tid; i < NBIN / 4; i += 512) h4[i] = z;
    }
    __syncthreads();
    for (int e = tid; e < TOT; e += 512) {
        uint32_t b = __float_as_uint(g_cls_scores[img * TOT + e]);
        uint32_t m = (b & 0x80000000u) ? ~b : (b | 0x80000000u);
        atomicAdd(&hist[m >> 18], 1u);
    }
    __syncthreads();

    uint32_t v = 0;
    #pragma unroll
    for (int b = 0; b < 32; b++) v += hist[tid * 32 + ((b + tid) & 31)];
    suffix_scan_512(v, sufp, wsum, wsuf, tid);

    {
        uint32_t cur = sufp[tid], nxt = sufp[tid + 1];
        if (cur >= MAXD && nxt < MAXD) {
            uint32_t run = nxt;
            int T = tid * 32;
            uint32_t above = nxt;
            for (int b = 31; b >= 0; b--) {
                uint32_t h = hist[tid * 32 + b];
                run += h;
                if (run >= MAXD) { T = tid * 32 + b; above = run - h; break; }
            }
            scal[5] = (uint32_t)T;
            scal[1] = above;
        }
        if (tid == 0) { scal[3] = 0; scal[4] = 0; }
    }
    __syncthreads();
    uint32_t T1    = scal[5];
    uint32_t above = scal[1];
    uint32_t need  = MAXD - above;

    {
        uint4 z = make_uint4(0, 0, 0, 0);
        uint4* h4 = (uint4*)hist;
        for (int i = tid; i < NBIN / 4; i += 512) h4[i] = z;
    }
    __syncthreads();
    for (int e = tid; e < TOT; e += 512) {
        uint32_t b = __float_as_uint(g_cls_scores[img * TOT + e]);
        uint32_t m = (b & 0x80000000u) ? ~b : (b | 0x80000000u);
        if ((m >> 18) == T1) atomicAdd(&hist[(m >> 4) & 0x3FFFu], 1u);
    }
    __syncthreads();

    v = 0;
    #pragma unroll
    for (int b = 0; b < 32; b++) v += hist[tid * 32 + ((b + tid) & 31)];
    suffix_scan_512(v, sufp, wsum, wsuf, tid);

    {
        uint32_t cur = sufp[tid], nxt = sufp[tid + 1];
        if (cur >= need && nxt < need) {
            uint32_t run = nxt;
            int T = tid * 32;
            for (int b = 31; b >= 0; b--) {
                run += hist[tid * 32 + b];
                if (run >= need) { T = tid * 32 + b; break; }
            }
            scal[2] = (uint32_t)T;
        }
    }
    __syncthreads();
    uint32_t T2 = scal[2];

    for (int e = tid; e < TOT; e += 512) {
        uint32_t b = __float_as_uint(g_cls_scores[img * TOT + e]);
        uint32_t m = (b & 0x80000000u) ? ~b : (b | 0x80000000u);
        uint32_t b1 = m >> 18;
        bool cand = (b1 > T1) || (b1 == T1 && ((m >> 4) & 0x3FFFu) >= T2);
        if (cand) {
            uint32_t p = atomicAdd(&scal[3], 1u);
            if (p < BUF_MRG)
                keys[p] = ((unsigned long long)m << 32) | (uint32_t)(~(uint32_t)e);
        }
    }
    __syncthreads();
    int C = (int)min(scal[3], (uint32_t)BUF_MRG);
    for (int i = tid; i < BUF_MRG; i += 512) if (i >= C) keys[i] = 0ull;
    __syncthreads();

    for (int k = 2; k <= BUF_MRG; k <<= 1) {
        for (int j = k >> 1; j > 0; j >>= 1) {
            for (int i = tid; i < BUF_MRG; i += 512) {
                int l = i ^ j;
                if (l > i) {
                    unsigned long long x = keys[i], y = keys[l];
                    bool up = ((i & k) == 0);
                    if (up ? (x > y) : (x < y)) { keys[i] = y; keys[l] = x; }
                }
            }
            __syncthreads();
        }
    }

    if (tid < MAXD) {
        unsigned long long key = keys[BUF_MRG - 1 - tid];
        uint32_t e = ~((uint32_t)key);
        float s  = g_cls_scores[img * TOT + e];
        float4 b = g_cls_boxes[img * TOT + e];
        bool valid = (s >= 0.05f);
        int cls = (int)(e / MAXPC);
        int o = img * MAXD + tid;
        float4 ob = valid ? b : make_float4(-1.0f, -1.0f, -1.0f, -1.0f);
        ((float4*)out)[o]  = ob;
        out[1600 + o] = valid ? s : -1.0f;
        out[2000 + o] = valid ? (float)cls : -1.0f;
        if (valid) atomicAdd(&scal[4], 1u);
    }
    __syncthreads();
    if (tid == 0) out[2400 + img] = (float)scal[4];
}

// ---------------- launcher ----------------
extern "C" void kernel_launch(void* const* d_in, const int* in_sizes, int n_in,
                              void* d_out, int out_size) {
    const float* pred = (const float*)d_in[1];
    if (n_in >= 1 && in_sizes[0] == N_IMG * N_ANCH * 84)
        pred = (const float*)d_in[0];

    cudaFuncSetAttribute(k_nms,   cudaFuncAttributeMaxDynamicSharedMemorySize, NMS_SMEM);
    cudaFuncSetAttribute(k_merge, cudaFuncAttributeMaxDynamicSharedMemorySize, MRG_SMEM);

    const int TOTV = N_IMG * N_ANCH * 21;
    k_zero<<<1, 512>>>();
    k_prep<<<(TOTV + 255) / 256, 256>>>(pred);
    k_nms<<<N_IMG * N_CLS, 512, NMS_SMEM>>>(pred);
    k_merge<<<N_IMG, 512, MRG_SMEM>>>((float*)d_out);
}